// round 11
// baseline (speedup 1.0000x reference)
#include <cuda_runtime.h>
#include <cuda_bf16.h>
#include <cuda_fp16.h>
#include <cstdint>

#define NB 8
#define NS 4096
#define NE 8
#define NROWS (NB * NS)
#define TILE 256            // keys per smem tile (double-buffered)

// Packed operand buffers (fragment-order layouts, all f16):
//  g_Q[row][4 w]: w_m = (q_{2m}, q_{2m+1}) f16x2, q pre-scaled by SCALE*log2e
//  g_K[row][4 w]: w_m = (k_{2m}, k_{2m+1}) f16x2
//  g_V2[pair][8 w]: w_e = {lo16 = f16 v_{2p,e}, hi16 = f16 v_{2p+1,e}}
__device__ __align__(16) uint32_t g_Q[NROWS * 4];
__device__ __align__(16) uint32_t g_K[NROWS * 4];
__device__ __align__(16) uint32_t g_V2[(NROWS / 2) * 8];

__device__ __forceinline__ float ex2f(float x) {
    float y; asm("ex2.approx.ftz.f32 %0, %1;" : "=f"(y) : "f"(x)); return y;
}
// 2^x on the FMA/ALU pipes: bits-trick exponent + cubic 2^frac.
// |x| <= 6.  rel err ~<= 8.5e-4 (below f16 quantization downstream).
__device__ __forceinline__ float ex2poly(float x) {
    const float C = 12582912.0f;          // 1.5 * 2^23
    float t = x + C;                      // mantissa holds round(x)
    float k = t - C;
    float f = x - k;                      // f in [-0.5, 0.5]
    float p = fmaf(f, 0.0555041086f, 0.2402265069f);   // ln2^3/6, ln2^2/2
    p = fmaf(f, p, 0.6931471806f);                     // ln2
    p = fmaf(f, p, 1.0f);                              // 2^f (cubic Taylor)
    uint32_t ib = __float_as_uint(t) << 23;            // = round(x) << 23
    return __uint_as_float(__float_as_uint(p) + ib);   // p * 2^round(x)
}
// f16x2 {lo, hi}
__device__ __forceinline__ uint32_t cvt2h(float lo, float hi) {
    uint32_t d; asm("cvt.rn.f16x2.f32 %0, %2, %1;" : "=r"(d) : "f"(lo), "f"(hi)); return d;
}
__device__ __forceinline__ void mma1688f16(
    float& d0, float& d1, float& d2, float& d3,
    uint32_t a0, uint32_t a1, uint32_t b0,
    float c0, float c1, float c2, float c3)
{
    asm("mma.sync.aligned.m16n8k8.row.col.f32.f16.f16.f32 "
        "{%0,%1,%2,%3},{%4,%5},{%6},{%7,%8,%9,%10};"
        : "=f"(d0), "=f"(d1), "=f"(d2), "=f"(d3)
        : "r"(a0), "r"(a1), "r"(b0),
          "f"(c0), "f"(c1), "f"(c2), "f"(c3));
}
__device__ __forceinline__ void mma16816f16(
    float& d0, float& d1, float& d2, float& d3,
    uint32_t a0, uint32_t a1, uint32_t a2, uint32_t a3,
    uint32_t b0, uint32_t b1,
    float c0, float c1, float c2, float c3)
{
    asm("mma.sync.aligned.m16n8k16.row.col.f32.f16.f16.f32 "
        "{%0,%1,%2,%3},{%4,%5,%6,%7},{%8,%9},{%10,%11,%12,%13};"
        : "=f"(d0), "=f"(d1), "=f"(d2), "=f"(d3)
        : "r"(a0), "r"(a1), "r"(a2), "r"(a3), "r"(b0), "r"(b1),
          "f"(c0), "f"(c1), "f"(c2), "f"(c3));
}
__device__ __forceinline__ void cpasync16(uint32_t smem_addr, const void* gptr) {
    asm volatile("cp.async.ca.shared.global [%0], [%1], 16;"
                 :: "r"(smem_addr), "l"(gptr));
}
__device__ __forceinline__ void cpcommit() {
    asm volatile("cp.async.commit_group;");
}
template<int N>
__device__ __forceinline__ void cpwait() {
    asm volatile("cp.async.wait_group %0;" :: "n"(N));
}

// ---------------------------------------------------------------------------
// Kernel 1: qkv projection + cos; 2 threads per row (4 output dims each).
// ---------------------------------------------------------------------------
__global__ void __launch_bounds__(256) qkv_kernel(
    const float* __restrict__ x,
    const float* __restrict__ Wq, const float* __restrict__ bq,
    const float* __restrict__ Wk, const float* __restrict__ bk,
    const float* __restrict__ Wv, const float* __restrict__ bv,
    const float* __restrict__ theta)
{
    __shared__ float sWq[64], sWk[64], sWv[64];
    __shared__ float sbq[8], sbk[8], sbv[8], sth[8];
    int tid = threadIdx.x;
    if (tid < 64) { sWq[tid] = Wq[tid]; sWk[tid] = Wk[tid]; sWv[tid] = Wv[tid]; }
    if (tid < 8)  { sbq[tid] = bq[tid]; sbk[tid] = bk[tid]; sbv[tid] = bv[tid]; sth[tid] = theta[tid]; }
    __syncthreads();

    int t = blockIdx.x * blockDim.x + tid;        // 0 .. 2*NROWS-1
    int r = t >> 1, half = t & 1, jb = half * 4;

    const float4* xp = (const float4*)(x + (size_t)r * 8);
    float4 xa = xp[0], xb = xp[1];
    float xr[8] = {xa.x, xa.y, xa.z, xa.w, xb.x, xb.y, xb.z, xb.w};

    const float QS = 0.5f * 1.4426950408889634f;  // SCALE * log2(e)
    float qo[4], ko[4];
    unsigned short vh[4];
#pragma unroll
    for (int jj = 0; jj < 4; jj++) {
        int j = jb + jj;
        float hq = sbq[j], hk = sbk[j], hv = sbv[j];
#pragma unroll
        for (int i = 0; i < 8; i++) {
            hq = fmaf(xr[i], sWq[j * 8 + i], hq);
            hk = fmaf(xr[i], sWk[j * 8 + i], hk);
            hv = fmaf(xr[i], sWv[j * 8 + i], hv);
        }
        float th = sth[j];
        qo[jj] = __cosf(hq + th) * QS;
        ko[jj] = __cosf(hk + th);
        float vv = __cosf(hv + th);
        __half hv16 = __float2half_rn(vv);
        vh[jj] = *(unsigned short*)&hv16;
    }
    uint2* Qd = (uint2*)(g_Q + (size_t)r * 4 + half * 2);
    *Qd = make_uint2(cvt2h(qo[0], qo[1]), cvt2h(qo[2], qo[3]));
    uint2* Kd = (uint2*)(g_K + (size_t)r * 4 + half * 2);
    *Kd = make_uint2(cvt2h(ko[0], ko[1]), cvt2h(ko[2], ko[3]));
    unsigned short* vb = (unsigned short*)(g_V2 + (size_t)(r >> 1) * 8);
    int rp = r & 1;
#pragma unroll
    for (int jj = 0; jj < 4; jj++)
        vb[(jb + jj) * 2 + rp] = vh[jj];
}

// ---------------------------------------------------------------------------
// Kernel 2: FA2-style attention. f16 m16n8k8 score MMAs, hybrid exp
// (5x MUFU ex2 + 3x FFMA-pipe poly), f16 P·V MMA, l via ones-MMA,
// cp.async double-buffered K/V, fused normalize + Wc epilogue.
// No max-subtraction (|score*log2e| <= 5.8).
// ---------------------------------------------------------------------------
__global__ void __launch_bounds__(128, 4) attn_kernel(
    const float* __restrict__ Wc, const float* __restrict__ bc,
    float* __restrict__ out)
{
    __shared__ uint32_t sK[2][TILE * 4];      // 4 KB per buffer
    __shared__ uint32_t sV[2][TILE * 4];      // 4 KB per buffer
    __shared__ float sWc[64], sbc[8];

    int tid = threadIdx.x;
    int warp = tid >> 5, lane = tid & 31;
    int g = lane >> 2, m = lane & 3;
    int b = blockIdx.y;
    int qbase = blockIdx.x * 64 + warp * 16;
    int rowg = b * NS + qbase + g;

    if (tid < 64) sWc[tid] = Wc[tid];
    if (tid < 8)  sbc[tid] = bc[tid];

    const uint32_t* Qr = g_Q + (size_t)rowg * 4;
    uint32_t qa0 = Qr[m];                     // row g,   e 2m,2m+1
    uint32_t qa1 = Qr[32 + m];                // row g+8

    float o0 = 0.f, o1 = 0.f, o2 = 0.f, o3 = 0.f;
    float la0 = 0.f, la1 = 0.f, la2 = 0.f, la3 = 0.f;
    const uint32_t ONE2 = 0x3C003C00u;        // f16x2 {1.0, 1.0}

    const uint4* Kg = (const uint4*)(g_K  + (size_t)b * NS * 4);
    const uint4* Vg = (const uint4*)(g_V2 + (size_t)b * (NS / 2) * 8);
    const int NT = NS / TILE;                 // 16 tiles
    const int U4 = TILE;                      // 256 uint4 per array per tile

    // issue tile 0 (2 uint4 per thread per array)
#pragma unroll
    for (int i = 0; i < 2; i++) {
        int idx = i * 128 + tid;
        cpasync16((uint32_t)__cvta_generic_to_shared(&((uint4*)sK[0])[idx]), Kg + idx);
        cpasync16((uint32_t)__cvta_generic_to_shared(&((uint4*)sV[0])[idx]), Vg + idx);
    }
    cpcommit();

    for (int t = 0; t < NT; t++) {
        int cur = t & 1;
        if (t + 1 < NT) {
            int nxt = cur ^ 1;
#pragma unroll
            for (int i = 0; i < 2; i++) {
                int idx = i * 128 + tid;
                cpasync16((uint32_t)__cvta_generic_to_shared(&((uint4*)sK[nxt])[idx]),
                          Kg + (t + 1) * U4 + idx);
                cpasync16((uint32_t)__cvta_generic_to_shared(&((uint4*)sV[nxt])[idx]),
                          Vg + (t + 1) * U4 + idx);
            }
            cpcommit();
            cpwait<1>();
        } else {
            cpwait<0>();
        }
        __syncthreads();

        const uint32_t* K = sK[cur];
        const uint32_t* V = sV[cur];
#pragma unroll 4
        for (int kt = 0; kt < TILE; kt += 16) {
            uint32_t kb0 = K[(kt + g) * 4 + m];       // key kt+g,   e 2m,2m+1
            uint32_t kb1 = K[(kt + 8 + g) * 4 + m];   // key kt+8+g
            float s0, s1, s2, s3, u0, u1, u2, u3;
            mma1688f16(s0, s1, s2, s3, qa0, qa1, kb0, 0.f, 0.f, 0.f, 0.f);
            mma1688f16(u0, u1, u2, u3, qa0, qa1, kb1, 0.f, 0.f, 0.f, 0.f);
            // Hybrid exp: 5 on MUFU, 3 on FMA/ALU pipes
            float p0 = ex2f(s0),    p1 = ex2poly(s1);
            float p2 = ex2f(s2),    p3 = ex2poly(s3);
            float r0 = ex2f(u0),    r1 = ex2poly(u1);
            float r2 = ex2f(u2),    r3 = ex2f(u3);
            uint32_t pa0 = cvt2h(p0, p1), pa1 = cvt2h(p2, p3);
            uint32_t pa2 = cvt2h(r0, r1), pa3 = cvt2h(r2, r3);
            uint32_t vb0 = V[((kt >> 1) + m) * 8 + g];
            uint32_t vb1 = V[((kt >> 1) + 4 + m) * 8 + g];
            mma16816f16(o0, o1, o2, o3, pa0, pa1, pa2, pa3, vb0, vb1, o0, o1, o2, o3);
            mma16816f16(la0, la1, la2, la3, pa0, pa1, pa2, pa3, ONE2, ONE2,
                        la0, la1, la2, la3);
        }
        __syncthreads();                      // before next issue overwrites buffer
    }

    // Epilogue: la0 = l(row g), la2 = l(row g+8) (ones-MMA: all cols equal).
    float invg = 1.0f / la0;
    float invh = 1.0f / la2;
    float* ep = (float*)sK + warp * 128;
    ep[g * 8 + 2 * m]           = o0 * invg;
    ep[g * 8 + 2 * m + 1]       = o1 * invg;
    ep[(g + 8) * 8 + 2 * m]     = o2 * invh;
    ep[(g + 8) * 8 + 2 * m + 1] = o3 * invh;
    __syncwarp();
    if (lane < 16) {
        const float4* rp = (const float4*)(ep + lane * 8);
        float4 va = rp[0], vbv = rp[1];
        float ov[8] = {va.x, va.y, va.z, va.w, vbv.x, vbv.y, vbv.z, vbv.w};
        float res[8];
#pragma unroll
        for (int j = 0; j < 8; j++) {
            float s = sbc[j];
#pragma unroll
            for (int e = 0; e < 8; e++)
                s = fmaf(ov[e], sWc[j * 8 + e], s);
            res[j] = s;
        }
        float4* op = (float4*)(out + ((size_t)b * NS + qbase + lane) * 8);
        op[0] = make_float4(res[0], res[1], res[2], res[3]);
        op[1] = make_float4(res[4], res[5], res[6], res[7]);
    }
}

// ---------------------------------------------------------------------------
extern "C" void kernel_launch(void* const* d_in, const int* in_sizes, int n_in,
                              void* d_out, int out_size)
{
    const float* x     = (const float*)d_in[0];
    const float* Wq    = (const float*)d_in[1];
    const float* bq    = (const float*)d_in[2];
    const float* Wk    = (const float*)d_in[3];
    const float* bk    = (const float*)d_in[4];
    const float* Wv    = (const float*)d_in[5];
    const float* bv    = (const float*)d_in[6];
    const float* theta = (const float*)d_in[7];
    const float* Wc    = (const float*)d_in[8];
    const float* bc    = (const float*)d_in[9];

    qkv_kernel<<<(2 * NROWS) / 256, 256>>>(x, Wq, bq, Wk, bk, Wv, bv, theta);

    dim3 grid(NS / 64, NB);                 // (64, 8) = 512 CTAs, 4 warps each
    attn_kernel<<<grid, 128>>>(Wc, bc, (float*)d_out);
}

// round 12
// speedup vs baseline: 1.2319x; 1.2319x over previous
#include <cuda_runtime.h>
#include <cuda_bf16.h>
#include <cuda_fp16.h>
#include <cstdint>

#define NB 8
#define NS 4096
#define NE 8
#define NROWS (NB * NS)
#define TILE 256            // keys per smem tile (triple-buffered)

// Packed operand buffers (fragment-order layouts, all f16):
//  g_K[row][4 w]: w_m = (k_{2m}, k_{2m+1}) f16x2
//  g_V2[pair][8 w]: w_e = {lo16 = f16 v_{2p,e}, hi16 = f16 v_{2p+1,e}}
__device__ __align__(16) uint32_t g_K[NROWS * 4];
__device__ __align__(16) uint32_t g_V2[(NROWS / 2) * 8];

__device__ __forceinline__ float ex2f(float x) {
    float y; asm("ex2.approx.ftz.f32 %0, %1;" : "=f"(y) : "f"(x)); return y;
}
// f16x2 {lo, hi}
__device__ __forceinline__ uint32_t cvt2h(float lo, float hi) {
    uint32_t d; asm("cvt.rn.f16x2.f32 %0, %2, %1;" : "=r"(d) : "f"(lo), "f"(hi)); return d;
}
__device__ __forceinline__ void mma1688f16(
    float& d0, float& d1, float& d2, float& d3,
    uint32_t a0, uint32_t a1, uint32_t b0,
    float c0, float c1, float c2, float c3)
{
    asm("mma.sync.aligned.m16n8k8.row.col.f32.f16.f16.f32 "
        "{%0,%1,%2,%3},{%4,%5},{%6},{%7,%8,%9,%10};"
        : "=f"(d0), "=f"(d1), "=f"(d2), "=f"(d3)
        : "r"(a0), "r"(a1), "r"(b0),
          "f"(c0), "f"(c1), "f"(c2), "f"(c3));
}
__device__ __forceinline__ void mma16816f16(
    float& d0, float& d1, float& d2, float& d3,
    uint32_t a0, uint32_t a1, uint32_t a2, uint32_t a3,
    uint32_t b0, uint32_t b1,
    float c0, float c1, float c2, float c3)
{
    asm("mma.sync.aligned.m16n8k16.row.col.f32.f16.f16.f32 "
        "{%0,%1,%2,%3},{%4,%5,%6,%7},{%8,%9},{%10,%11,%12,%13};"
        : "=f"(d0), "=f"(d1), "=f"(d2), "=f"(d3)
        : "r"(a0), "r"(a1), "r"(a2), "r"(a3), "r"(b0), "r"(b1),
          "f"(c0), "f"(c1), "f"(c2), "f"(c3));
}
__device__ __forceinline__ void cpasync16(uint32_t smem_addr, const void* gptr) {
    asm volatile("cp.async.ca.shared.global [%0], [%1], 16;"
                 :: "r"(smem_addr), "l"(gptr));
}
__device__ __forceinline__ void cpcommit() {
    asm volatile("cp.async.commit_group;");
}
template<int N>
__device__ __forceinline__ void cpwait() {
    asm volatile("cp.async.wait_group %0;" :: "n"(N));
}

// ---------------------------------------------------------------------------
// Kernel 1: K/V projection + cos; 2 threads per row (4 output dims each).
// (Q is computed inside the attention kernel's prologue.)
// ---------------------------------------------------------------------------
__global__ void __launch_bounds__(256) kv_kernel(
    const float* __restrict__ x,
    const float* __restrict__ Wk, const float* __restrict__ bk,
    const float* __restrict__ Wv, const float* __restrict__ bv,
    const float* __restrict__ theta)
{
    __shared__ float sWk[64], sWv[64];
    __shared__ float sbk[8], sbv[8], sth[8];
    int tid = threadIdx.x;
    if (tid < 64) { sWk[tid] = Wk[tid]; sWv[tid] = Wv[tid]; }
    if (tid < 8)  { sbk[tid] = bk[tid]; sbv[tid] = bv[tid]; sth[tid] = theta[tid]; }
    __syncthreads();

    int t = blockIdx.x * blockDim.x + tid;        // 0 .. 2*NROWS-1
    int r = t >> 1, half = t & 1, jb = half * 4;

    const float4* xp = (const float4*)(x + (size_t)r * 8);
    float4 xa = xp[0], xb = xp[1];
    float xr[8] = {xa.x, xa.y, xa.z, xa.w, xb.x, xb.y, xb.z, xb.w};

    float ko[4];
    unsigned short vh[4];
#pragma unroll
    for (int jj = 0; jj < 4; jj++) {
        int j = jb + jj;
        float hk = sbk[j], hv = sbv[j];
#pragma unroll
        for (int i = 0; i < 8; i++) {
            hk = fmaf(xr[i], sWk[j * 8 + i], hk);
            hv = fmaf(xr[i], sWv[j * 8 + i], hv);
        }
        float th = sth[j];
        ko[jj] = __cosf(hk + th);
        float vv = __cosf(hv + th);
        __half hv16 = __float2half_rn(vv);
        vh[jj] = *(unsigned short*)&hv16;
    }
    uint2* Kd = (uint2*)(g_K + (size_t)r * 4 + half * 2);
    *Kd = make_uint2(cvt2h(ko[0], ko[1]), cvt2h(ko[2], ko[3]));
    unsigned short* vb = (unsigned short*)(g_V2 + (size_t)(r >> 1) * 8);
    int rp = r & 1;
#pragma unroll
    for (int jj = 0; jj < 4; jj++)
        vb[(jb + jj) * 2 + rp] = vh[jj];
}

// ---------------------------------------------------------------------------
// Kernel 2: FA2-style attention. Q projected in-prologue (overlapped with
// tile-0 cp.async), f16 m16n8k8 score MMAs, 8x f32 ex2, f16 P·V MMA,
// l via ones-MMA, triple-buffered cp.async K/V ring (single barrier/tile),
// fused normalize + Wc epilogue.  No max-subtraction (|score*log2e| <= 5.8).
// ---------------------------------------------------------------------------
__global__ void __launch_bounds__(128, 4) attn_kernel(
    const float* __restrict__ x,
    const float* __restrict__ Wq, const float* __restrict__ bq,
    const float* __restrict__ theta,
    const float* __restrict__ Wc, const float* __restrict__ bc,
    float* __restrict__ out)
{
    __shared__ uint32_t sK[3][TILE * 4];      // 4 KB per buffer
    __shared__ uint32_t sV[3][TILE * 4];      // 4 KB per buffer
    __shared__ uint32_t sQ[64 * 4];           // 1 KB: per-CTA Q fragments
    __shared__ float sEp[512];                // 2 KB: epilogue scratch
    __shared__ float sWc[64], sbc[8];

    int tid = threadIdx.x;
    int warp = tid >> 5, lane = tid & 31;
    int g = lane >> 2, m = lane & 3;
    int b = blockIdx.y;
    int qbase = blockIdx.x * 64 + warp * 16;

    if (tid < 64) sWc[tid] = Wc[tid];
    if (tid < 8)  sbc[tid] = bc[tid];

    const uint4* Kg = (const uint4*)(g_K  + (size_t)b * NS * 4);
    const uint4* Vg = (const uint4*)(g_V2 + (size_t)b * (NS / 2) * 8);
    const int NT = NS / TILE;                 // 16 tiles
    const int U4 = TILE;                      // 256 uint4 per array per tile

    // issue tile 0 (2 uint4 per thread per array)
#pragma unroll
    for (int i = 0; i < 2; i++) {
        int idx = i * 128 + tid;
        cpasync16((uint32_t)__cvta_generic_to_shared(&((uint4*)sK[0])[idx]), Kg + idx);
        cpasync16((uint32_t)__cvta_generic_to_shared(&((uint4*)sV[0])[idx]), Vg + idx);
    }
    cpcommit();

    // ---- Q prologue (overlaps tile-0 cp.async): 128 threads = 64 rows x 2 halves
    {
        const float QS = 0.5f * 1.4426950408889634f;  // SCALE * log2(e)
        int qrow = tid >> 1, qhalf = tid & 1, jb = qhalf * 4;
        int grow = b * NS + blockIdx.x * 64 + qrow;
        const float4* xp = (const float4*)(x + (size_t)grow * 8);
        float4 xa = xp[0], xb = xp[1];
        float xr[8] = {xa.x, xa.y, xa.z, xa.w, xb.x, xb.y, xb.z, xb.w};
        float qo[4];
#pragma unroll
        for (int jj = 0; jj < 4; jj++) {
            int j = jb + jj;
            float acc = __ldg(&bq[j]);
#pragma unroll
            for (int i = 0; i < 8; i++)
                acc = fmaf(xr[i], __ldg(&Wq[j * 8 + i]), acc);
            qo[jj] = __cosf(acc + __ldg(&theta[j])) * QS;
        }
        sQ[qrow * 4 + qhalf * 2]     = cvt2h(qo[0], qo[1]);
        sQ[qrow * 4 + qhalf * 2 + 1] = cvt2h(qo[2], qo[3]);
    }
    __syncthreads();
    uint32_t qa0 = sQ[(warp * 16 + g) * 4 + m];       // row g,   e 2m,2m+1
    uint32_t qa1 = sQ[(warp * 16 + 8 + g) * 4 + m];   // row g+8

    float o0 = 0.f, o1 = 0.f, o2 = 0.f, o3 = 0.f;
    float la0 = 0.f, la1 = 0.f, la2 = 0.f, la3 = 0.f;
    const uint32_t ONE2 = 0x3C003C00u;        // f16x2 {1.0, 1.0}

    for (int t = 0; t < NT; t++) {
        int cur = t % 3;
        if (t + 1 < NT) {
            int nxt = (t + 1) % 3;
#pragma unroll
            for (int i = 0; i < 2; i++) {
                int idx = i * 128 + tid;
                cpasync16((uint32_t)__cvta_generic_to_shared(&((uint4*)sK[nxt])[idx]),
                          Kg + (t + 1) * U4 + idx);
                cpasync16((uint32_t)__cvta_generic_to_shared(&((uint4*)sV[nxt])[idx]),
                          Vg + (t + 1) * U4 + idx);
            }
            cpcommit();
            cpwait<1>();
        } else {
            cpwait<0>();
        }
        __syncthreads();   // data visible; also proves all warps left tile t-1

        const uint32_t* K = sK[cur];
        const uint32_t* V = sV[cur];
#pragma unroll 4
        for (int kt = 0; kt < TILE; kt += 16) {
            uint32_t kb0 = K[(kt + g) * 4 + m];       // key kt+g,   e 2m,2m+1
            uint32_t kb1 = K[(kt + 8 + g) * 4 + m];   // key kt+8+g
            float s0, s1, s2, s3, u0, u1, u2, u3;
            mma1688f16(s0, s1, s2, s3, qa0, qa1, kb0, 0.f, 0.f, 0.f, 0.f);
            mma1688f16(u0, u1, u2, u3, qa0, qa1, kb1, 0.f, 0.f, 0.f, 0.f);
            float p0 = ex2f(s0), p1 = ex2f(s1), p2 = ex2f(s2), p3 = ex2f(s3);
            float r0 = ex2f(u0), r1 = ex2f(u1), r2 = ex2f(u2), r3 = ex2f(u3);
            uint32_t pa0 = cvt2h(p0, p1), pa1 = cvt2h(p2, p3);
            uint32_t pa2 = cvt2h(r0, r1), pa3 = cvt2h(r2, r3);
            uint32_t vb0 = V[((kt >> 1) + m) * 8 + g];
            uint32_t vb1 = V[((kt >> 1) + 4 + m) * 8 + g];
            mma16816f16(o0, o1, o2, o3, pa0, pa1, pa2, pa3, vb0, vb1, o0, o1, o2, o3);
            mma16816f16(la0, la1, la2, la3, pa0, pa1, pa2, pa3, ONE2, ONE2,
                        la0, la1, la2, la3);
        }
        // no trailing barrier: 3-buffer ring + next leading barrier covers reuse
    }

    // Epilogue: la0 = l(row g), la2 = l(row g+8) (ones-MMA: all cols equal).
    float invg = 1.0f / la0;
    float invh = 1.0f / la2;
    float* ep = sEp + warp * 128;             // private per warp
    ep[g * 8 + 2 * m]           = o0 * invg;
    ep[g * 8 + 2 * m + 1]       = o1 * invg;
    ep[(g + 8) * 8 + 2 * m]     = o2 * invh;
    ep[(g + 8) * 8 + 2 * m + 1] = o3 * invh;
    __syncwarp();
    if (lane < 16) {
        const float4* rp = (const float4*)(ep + lane * 8);
        float4 va = rp[0], vbv = rp[1];
        float ov[8] = {va.x, va.y, va.z, va.w, vbv.x, vbv.y, vbv.z, vbv.w};
        float res[8];
#pragma unroll
        for (int j = 0; j < 8; j++) {
            float s = sbc[j];
#pragma unroll
            for (int e = 0; e < 8; e++)
                s = fmaf(ov[e], sWc[j * 8 + e], s);
            res[j] = s;
        }
        float4* op = (float4*)(out + ((size_t)b * NS + qbase + lane) * 8);
        op[0] = make_float4(res[0], res[1], res[2], res[3]);
        op[1] = make_float4(res[4], res[5], res[6], res[7]);
    }
}

// ---------------------------------------------------------------------------
extern "C" void kernel_launch(void* const* d_in, const int* in_sizes, int n_in,
                              void* d_out, int out_size)
{
    const float* x     = (const float*)d_in[0];
    const float* Wq    = (const float*)d_in[1];
    const float* bq    = (const float*)d_in[2];
    const float* Wk    = (const float*)d_in[3];
    const float* bk    = (const float*)d_in[4];
    const float* Wv    = (const float*)d_in[5];
    const float* bv    = (const float*)d_in[6];
    const float* theta = (const float*)d_in[7];
    const float* Wc    = (const float*)d_in[8];
    const float* bc    = (const float*)d_in[9];

    kv_kernel<<<(2 * NROWS) / 256, 256>>>(x, Wk, bk, Wv, bv, theta);

    dim3 grid(NS / 64, NB);                 // (64, 8) = 512 CTAs, 4 warps each
    attn_kernel<<<grid, 128>>>(x, Wq, bq, theta, Wc, bc, (float*)d_out);
}